// round 1
// baseline (speedup 1.0000x reference)
#include <cuda_runtime.h>

#define NPOOL 100000
#define NUN   200000
#define NEDGE 1200000
#define CH    64
#define EPSV  1e-5f

// ---------------- scratch (static device globals; no allocation) ----------------
__device__ float  g_P  [NPOOL * CH];   // x @ W1                 (25.6 MB)
__device__ float  g_Y  [NUN * CH];     // unpool(P)/score + b1   (51.2 MB)
__device__ float  g_HW [NUN * CH];     // relu(bn(Y)) @ Wg       (51.2 MB)
__device__ float  g_ACC[NUN * CH];     // GCN accumulator        (51.2 MB)
__device__ float  g_deg[NUN];
__device__ float  g_dis[NUN];
__device__ double g_s1[CH], g_q1[CH], g_s2[CH], g_q2[CH];
__device__ float  g_scale1[CH], g_shift1[CH], g_scale2[CH], g_shift2[CH];

// ---------------- init ----------------
__global__ void k_zero() {
    int i = blockIdx.x * blockDim.x + threadIdx.x;
    if (i < NUN) g_deg[i] = 0.f;
    if (i < CH) { g_s1[i] = 0.0; g_q1[i] = 0.0; g_s2[i] = 0.0; g_q2[i] = 0.0; }
}

// ---------------- degree from edges (dst), then dis = rsqrt(indeg + 1) ----------------
__global__ void k_deg(const int* __restrict__ dst) {
    int i = blockIdx.x * blockDim.x + threadIdx.x;
    if (i < NEDGE) atomicAdd(&g_deg[dst[i]], 1.0f);
}

__global__ void k_dis() {
    int i = blockIdx.x * blockDim.x + threadIdx.x;
    if (i < NUN) g_dis[i] = rsqrtf(g_deg[i] + 1.0f);
}

// ---------------- GEMM1: P = x @ W1   (NPOOL x 64 x 64) ----------------
// 128 threads, 64 rows/block. Thread: 8 cols (cg*8) x 4 rows (rg + 16*r).
__global__ __launch_bounds__(128) void k_gemm1(const float* __restrict__ x,
                                               const float* __restrict__ W) {
    __shared__ float Ws[64 * 64];
    __shared__ float Xs[64 * 68];
    int t = threadIdx.x;
    for (int i = t; i < 1024; i += 128)
        ((float4*)Ws)[i] = ((const float4*)W)[i];
    int row0 = blockIdx.x * 64;
    for (int i = t; i < 1024; i += 128) {
        int r = i >> 4, c4 = i & 15;
        int row = row0 + r;
        float4 v = make_float4(0.f, 0.f, 0.f, 0.f);
        if (row < NPOOL) v = ((const float4*)(x + (size_t)row * CH))[c4];
        *((float4*)(Xs + r * 68 + c4 * 4)) = v;
    }
    __syncthreads();
    int cg = t & 7, rg = t >> 3;
    float acc[4][8];
#pragma unroll
    for (int r = 0; r < 4; r++)
#pragma unroll
        for (int c = 0; c < 8; c++) acc[r][c] = 0.f;
    for (int k = 0; k < 64; k++) {
        float4 w0 = *((float4*)(Ws + k * 64 + cg * 8));
        float4 w1 = *((float4*)(Ws + k * 64 + cg * 8 + 4));
#pragma unroll
        for (int r = 0; r < 4; r++) {
            float xv = Xs[(rg + 16 * r) * 68 + k];
            acc[r][0] = fmaf(xv, w0.x, acc[r][0]);
            acc[r][1] = fmaf(xv, w0.y, acc[r][1]);
            acc[r][2] = fmaf(xv, w0.z, acc[r][2]);
            acc[r][3] = fmaf(xv, w0.w, acc[r][3]);
            acc[r][4] = fmaf(xv, w1.x, acc[r][4]);
            acc[r][5] = fmaf(xv, w1.y, acc[r][5]);
            acc[r][6] = fmaf(xv, w1.z, acc[r][6]);
            acc[r][7] = fmaf(xv, w1.w, acc[r][7]);
        }
    }
#pragma unroll
    for (int r = 0; r < 4; r++) {
        int row = row0 + rg + 16 * r;
        if (row < NPOOL) {
            size_t base = (size_t)row * CH + cg * 8;
            *((float4*)(g_P + base))     = make_float4(acc[r][0], acc[r][1], acc[r][2], acc[r][3]);
            *((float4*)(g_P + base + 4)) = make_float4(acc[r][4], acc[r][5], acc[r][6], acc[r][7]);
        }
    }
}

// ---------------- unpool: Y = P[cluster]/score[cluster] + b1 ; accumulate BN1 stats ----------------
__global__ void k_unpool(const int* __restrict__ cluster, const float* __restrict__ score,
                         const float* __restrict__ b1) {
    int tx = threadIdx.x;   // 64: column
    int ty = threadIdx.y;   // 4
    int row0 = blockIdx.x * 64;
    float bias = b1[tx];
    float ls = 0.f, lq = 0.f;
    for (int r = 0; r < 16; r++) {
        int row = row0 + ty + 4 * r;
        if (row < NUN) {
            int c = cluster[row];
            float inv = 1.0f / score[c];
            float v = fmaf(g_P[(size_t)c * CH + tx], inv, bias);
            g_Y[(size_t)row * CH + tx] = v;
            ls += v;
            lq += v * v;
        }
    }
    __shared__ float ss[4][64], sq[4][64];
    ss[ty][tx] = ls; sq[ty][tx] = lq;
    __syncthreads();
    if (ty == 0) {
        float s = ss[0][tx] + ss[1][tx] + ss[2][tx] + ss[3][tx];
        float q = sq[0][tx] + sq[1][tx] + sq[2][tx] + sq[3][tx];
        atomicAdd(&g_s1[tx], (double)s);
        atomicAdd(&g_q1[tx], (double)q);
    }
}

// ---------------- finalize BN params: scale = g*rsqrt(var+eps), shift = beta - mu*scale ----------------
__global__ void k_meanvar(const float* __restrict__ g, const float* __restrict__ b, int which) {
    int t = threadIdx.x;
    if (t < CH) {
        double s = which ? g_s2[t] : g_s1[t];
        double q = which ? g_q2[t] : g_q1[t];
        double invN = 1.0 / (double)NUN;
        float mu = (float)(s * invN);
        float var = (float)(q * invN) - mu * mu;
        if (var < 0.f) var = 0.f;
        float rs = rsqrtf(var + EPSV);
        float sc = g[t] * rs;
        float sh = b[t] - mu * sc;
        if (which) { g_scale2[t] = sc; g_shift2[t] = sh; }
        else       { g_scale1[t] = sc; g_shift1[t] = sh; }
    }
}

// ---------------- GEMM2: HW = relu(bn1(Y)) @ Wg ; ACC = bg + HW * dis^2 (self loop) ----------------
__global__ __launch_bounds__(128) void k_gemm2(const float* __restrict__ Wg,
                                               const float* __restrict__ bgv) {
    __shared__ float Ws[64 * 64];
    __shared__ float Xs[64 * 68];
    int t = threadIdx.x;
    for (int i = t; i < 1024; i += 128)
        ((float4*)Ws)[i] = ((const float4*)Wg)[i];
    int row0 = blockIdx.x * 64;
    for (int i = t; i < 1024; i += 128) {
        int r = i >> 4, c4 = i & 15;
        int row = row0 + r;
        float4 v = make_float4(0.f, 0.f, 0.f, 0.f);
        if (row < NUN) {
            float4 y  = ((const float4*)(g_Y + (size_t)row * CH))[c4];
            float4 sc = ((const float4*)g_scale1)[c4];
            float4 sh = ((const float4*)g_shift1)[c4];
            v.x = fmaxf(fmaf(y.x, sc.x, sh.x), 0.f);
            v.y = fmaxf(fmaf(y.y, sc.y, sh.y), 0.f);
            v.z = fmaxf(fmaf(y.z, sc.z, sh.z), 0.f);
            v.w = fmaxf(fmaf(y.w, sc.w, sh.w), 0.f);
        }
        *((float4*)(Xs + r * 68 + c4 * 4)) = v;
    }
    __syncthreads();
    int cg = t & 7, rg = t >> 3;
    float acc[4][8];
#pragma unroll
    for (int r = 0; r < 4; r++)
#pragma unroll
        for (int c = 0; c < 8; c++) acc[r][c] = 0.f;
    for (int k = 0; k < 64; k++) {
        float4 w0 = *((float4*)(Ws + k * 64 + cg * 8));
        float4 w1 = *((float4*)(Ws + k * 64 + cg * 8 + 4));
#pragma unroll
        for (int r = 0; r < 4; r++) {
            float xv = Xs[(rg + 16 * r) * 68 + k];
            acc[r][0] = fmaf(xv, w0.x, acc[r][0]);
            acc[r][1] = fmaf(xv, w0.y, acc[r][1]);
            acc[r][2] = fmaf(xv, w0.z, acc[r][2]);
            acc[r][3] = fmaf(xv, w0.w, acc[r][3]);
            acc[r][4] = fmaf(xv, w1.x, acc[r][4]);
            acc[r][5] = fmaf(xv, w1.y, acc[r][5]);
            acc[r][6] = fmaf(xv, w1.z, acc[r][6]);
            acc[r][7] = fmaf(xv, w1.w, acc[r][7]);
        }
    }
    float4 b0 = *((const float4*)(bgv + cg * 8));
    float4 b1v = *((const float4*)(bgv + cg * 8 + 4));
#pragma unroll
    for (int r = 0; r < 4; r++) {
        int row = row0 + rg + 16 * r;
        if (row < NUN) {
            float dv = g_dis[row];
            float d2 = dv * dv;
            size_t base = (size_t)row * CH + cg * 8;
            float4 h0 = make_float4(acc[r][0], acc[r][1], acc[r][2], acc[r][3]);
            float4 h1 = make_float4(acc[r][4], acc[r][5], acc[r][6], acc[r][7]);
            *((float4*)(g_HW + base))     = h0;
            *((float4*)(g_HW + base + 4)) = h1;
            *((float4*)(g_ACC + base))     = make_float4(fmaf(h0.x, d2, b0.x),  fmaf(h0.y, d2, b0.y),
                                                         fmaf(h0.z, d2, b0.z),  fmaf(h0.w, d2, b0.w));
            *((float4*)(g_ACC + base + 4)) = make_float4(fmaf(h1.x, d2, b1v.x), fmaf(h1.y, d2, b1v.y),
                                                         fmaf(h1.z, d2, b1v.z), fmaf(h1.w, d2, b1v.w));
        }
    }
}

// ---------------- edge scatter: ACC[dst] += HW[src] * dis[src]*dis[dst]  (vector red) ----------------
__global__ void k_scatter(const int* __restrict__ src, const int* __restrict__ dst) {
    int tid = blockIdx.x * blockDim.x + threadIdx.x;   // NEDGE*16 threads
    if (tid < NEDGE * 16) {
        int e = tid >> 4;
        int q = tid & 15;
        int s = src[e], d = dst[e];
        float coef = g_dis[s] * g_dis[d];
        float4 v = *((const float4*)(g_HW + (size_t)s * CH + q * 4));
        float* p = g_ACC + (size_t)d * CH + q * 4;
        asm volatile("red.global.add.v4.f32 [%0], {%1, %2, %3, %4};"
                     :: "l"(p), "f"(v.x * coef), "f"(v.y * coef),
                        "f"(v.z * coef), "f"(v.w * coef)
                     : "memory");
    }
}

// ---------------- BN2 stats over ACC ----------------
__global__ void k_stats2() {
    int tx = threadIdx.x;
    int ty = threadIdx.y;
    int row0 = blockIdx.x * 64;
    float ls = 0.f, lq = 0.f;
    for (int r = 0; r < 16; r++) {
        int row = row0 + ty + 4 * r;
        if (row < NUN) {
            float v = g_ACC[(size_t)row * CH + tx];
            ls += v;
            lq += v * v;
        }
    }
    __shared__ float ss[4][64], sq[4][64];
    ss[ty][tx] = ls; sq[ty][tx] = lq;
    __syncthreads();
    if (ty == 0) {
        float s = ss[0][tx] + ss[1][tx] + ss[2][tx] + ss[3][tx];
        float q = sq[0][tx] + sq[1][tx] + sq[2][tx] + sq[3][tx];
        atomicAdd(&g_s2[tx], (double)s);
        atomicAdd(&g_q2[tx], (double)q);
    }
}

// ---------------- final: out = relu(bn2(ACC)) ----------------
__global__ void k_final(float* __restrict__ out) {
    int i4 = blockIdx.x * blockDim.x + threadIdx.x;   // NUN*16 float4s
    if (i4 < NUN * 16) {
        int c4 = i4 & 15;
        float4 v  = ((const float4*)g_ACC)[i4];
        float4 sc = ((const float4*)g_scale2)[c4];
        float4 sh = ((const float4*)g_shift2)[c4];
        float4 o;
        o.x = fmaxf(fmaf(v.x, sc.x, sh.x), 0.f);
        o.y = fmaxf(fmaf(v.y, sc.y, sh.y), 0.f);
        o.z = fmaxf(fmaf(v.z, sc.z, sh.z), 0.f);
        o.w = fmaxf(fmaf(v.w, sc.w, sh.w), 0.f);
        ((float4*)out)[i4] = o;
    }
}

// ---------------- optional tail: edge_index and batch passthrough (as float) ----------------
__global__ void k_tail(const int* __restrict__ ei, const int* __restrict__ batch,
                       float* __restrict__ out, int extra) {
    int i = blockIdx.x * blockDim.x + threadIdx.x;
    if (i < extra) {
        float v;
        if (i < 2 * NEDGE) v = (float)ei[i];
        else {
            int j = i - 2 * NEDGE;
            v = (j < NUN) ? (float)batch[j] : 0.f;
        }
        out[NUN * CH + i] = v;
    }
}

// ---------------- launch ----------------
extern "C" void kernel_launch(void* const* d_in, const int* in_sizes, int n_in,
                              void* d_out, int out_size) {
    const float* x       = (const float*)d_in[0];
    const int*   ei      = (const int*)  d_in[1];
    const int*   batch   = (const int*)  d_in[2];
    const int*   cluster = (const int*)  d_in[3];
    const float* score   = (const float*)d_in[4];
    const float* W1      = (const float*)d_in[5];
    const float* b1      = (const float*)d_in[6];
    const float* g1      = (const float*)d_in[7];
    const float* be1     = (const float*)d_in[8];
    const float* Wg      = (const float*)d_in[9];
    const float* bg      = (const float*)d_in[10];
    const float* g2      = (const float*)d_in[11];
    const float* be2     = (const float*)d_in[12];
    const int* srcA = ei;
    const int* dstA = ei + NEDGE;
    float* out = (float*)d_out;

    k_zero<<<(NUN + 255) / 256, 256>>>();
    k_deg<<<(NEDGE + 255) / 256, 256>>>(dstA);
    k_dis<<<(NUN + 255) / 256, 256>>>();
    k_gemm1<<<(NPOOL + 63) / 64, 128>>>(x, W1);
    k_unpool<<<(NUN + 63) / 64, dim3(64, 4)>>>(cluster, score, b1);
    k_meanvar<<<1, 64>>>(g1, be1, 0);
    k_gemm2<<<(NUN + 63) / 64, 128>>>(Wg, bg);
    k_scatter<<<(NEDGE * 16 + 255) / 256, 256>>>(srcA, dstA);
    k_stats2<<<(NUN + 63) / 64, dim3(64, 4)>>>();
    k_meanvar<<<1, 64>>>(g2, be2, 1);
    k_final<<<(NUN * 16 + 255) / 256, 256>>>(out);

    int extra = out_size - NUN * CH;
    if (extra > 0)
        k_tail<<<(extra + 255) / 256, 256>>>(ei, batch, out, extra);
}

// round 3
// speedup vs baseline: 1.0323x; 1.0323x over previous
#include <cuda_runtime.h>

#define NPOOL 100000
#define NUN   200000
#define NEDGE 1200000
#define CH    64
#define EPSV  1e-5f

// ---------------- scratch ----------------
__device__ float  g_P  [NPOOL * CH];   // x @ W1                       (25.6 MB)
__device__ float  g_HWp[NPOOL * CH];   // relu(bn1(P/score+b1)) @ Wg   (25.6 MB)
__device__ float  g_ACC[NUN * CH];     // GCN accumulator              (51.2 MB)
__device__ float  g_deg[NUN];
__device__ float  g_dis[NUN];
__device__ int    g_cnt[NPOOL];        // cluster multiplicity
__device__ double g_s1[CH], g_q1[CH], g_s2[CH], g_q2[CH];
__device__ float  g_scale1[CH], g_shift1[CH], g_scale2[CH], g_shift2[CH];

// ---------------- init ----------------
__global__ void k_init() {
    int i = blockIdx.x * blockDim.x + threadIdx.x;
    if (i < NUN)   g_deg[i] = 0.f;
    if (i < NPOOL) g_cnt[i] = 0;
    if (i < CH) { g_s1[i] = 0.0; g_q1[i] = 0.0; g_s2[i] = 0.0; g_q2[i] = 0.0; }
}

// ---------------- degree (dst) + cluster histogram ----------------
__global__ void k_deg_hist(const int* __restrict__ dst, const int* __restrict__ cluster) {
    int i = blockIdx.x * blockDim.x + threadIdx.x;
    if (i < NEDGE) atomicAdd(&g_deg[dst[i]], 1.0f);
    if (i < NUN)   atomicAdd(&g_cnt[cluster[i]], 1);
}

__global__ void k_dis() {
    int i = blockIdx.x * blockDim.x + threadIdx.x;
    if (i < NUN) g_dis[i] = rsqrtf(g_deg[i] + 1.0f);
}

// ---------------- GEMM1: P = x @ W1   (NPOOL x 64 x 64) ----------------
// 128 threads, 64 rows/block. Thread: 8 cols (cg*8) x 4 rows (rg + 16*r).
__global__ __launch_bounds__(128) void k_gemm1(const float* __restrict__ x,
                                               const float* __restrict__ W) {
    __shared__ float Ws[64 * 64];
    __shared__ float Xs[64 * 68];
    int t = threadIdx.x;
    for (int i = t; i < 1024; i += 128)
        ((float4*)Ws)[i] = ((const float4*)W)[i];
    int row0 = blockIdx.x * 64;
    for (int i = t; i < 1024; i += 128) {
        int r = i >> 4, c4 = i & 15;
        int row = row0 + r;
        float4 v = make_float4(0.f, 0.f, 0.f, 0.f);
        if (row < NPOOL) v = ((const float4*)(x + (size_t)row * CH))[c4];
        *((float4*)(Xs + r * 68 + c4 * 4)) = v;
    }
    __syncthreads();
    int cg = t & 7, rg = t >> 3;
    float acc[4][8];
#pragma unroll
    for (int r = 0; r < 4; r++)
#pragma unroll
        for (int c = 0; c < 8; c++) acc[r][c] = 0.f;
    for (int k = 0; k < 64; k++) {
        float4 w0 = *((float4*)(Ws + k * 64 + cg * 8));
        float4 w1 = *((float4*)(Ws + k * 64 + cg * 8 + 4));
#pragma unroll
        for (int r = 0; r < 4; r++) {
            float xv = Xs[(rg + 16 * r) * 68 + k];
            acc[r][0] = fmaf(xv, w0.x, acc[r][0]);
            acc[r][1] = fmaf(xv, w0.y, acc[r][1]);
            acc[r][2] = fmaf(xv, w0.z, acc[r][2]);
            acc[r][3] = fmaf(xv, w0.w, acc[r][3]);
            acc[r][4] = fmaf(xv, w1.x, acc[r][4]);
            acc[r][5] = fmaf(xv, w1.y, acc[r][5]);
            acc[r][6] = fmaf(xv, w1.z, acc[r][6]);
            acc[r][7] = fmaf(xv, w1.w, acc[r][7]);
        }
    }
#pragma unroll
    for (int r = 0; r < 4; r++) {
        int row = row0 + rg + 16 * r;
        if (row < NPOOL) {
            size_t base = (size_t)row * CH + cg * 8;
            *((float4*)(g_P + base))     = make_float4(acc[r][0], acc[r][1], acc[r][2], acc[r][3]);
            *((float4*)(g_P + base + 4)) = make_float4(acc[r][4], acc[r][5], acc[r][6], acc[r][7]);
        }
    }
}

// ---------------- BN1 stats from P, weighted by cnt ----------------
// sum_Y[col] = sum_c cnt[c]*(P[c]/score[c] + b1[col]); same for squares.
__global__ void k_stats1(const float* __restrict__ score, const float* __restrict__ b1) {
    int tx = threadIdx.x;   // col
    int ty = threadIdx.y;   // 4
    int row0 = blockIdx.x * 64;
    float bias = b1[tx];
    float ls = 0.f, lq = 0.f;
    for (int r = 0; r < 16; r++) {
        int row = row0 + ty + 4 * r;
        if (row < NPOOL) {
            int w = g_cnt[row];
            if (w > 0) {
                float inv = 1.0f / score[row];
                float v = fmaf(g_P[(size_t)row * CH + tx], inv, bias);
                float fw = (float)w;
                ls = fmaf(fw, v, ls);
                lq = fmaf(fw * v, v, lq);
            }
        }
    }
    __shared__ float ss[4][64], sq[4][64];
    ss[ty][tx] = ls; sq[ty][tx] = lq;
    __syncthreads();
    if (ty == 0) {
        float s = ss[0][tx] + ss[1][tx] + ss[2][tx] + ss[3][tx];
        float q = sq[0][tx] + sq[1][tx] + sq[2][tx] + sq[3][tx];
        atomicAdd(&g_s1[tx], (double)s);
        atomicAdd(&g_q1[tx], (double)q);
    }
}

// ---------------- finalize BN params ----------------
__global__ void k_meanvar(const float* __restrict__ g, const float* __restrict__ b, int which) {
    int t = threadIdx.x;
    if (t < CH) {
        double s = which ? g_s2[t] : g_s1[t];
        double q = which ? g_q2[t] : g_q1[t];
        double invN = 1.0 / (double)NUN;
        float mu = (float)(s * invN);
        float var = (float)(q * invN) - mu * mu;
        if (var < 0.f) var = 0.f;
        float rs = rsqrtf(var + EPSV);
        float sc = g[t] * rs;
        float sh = b[t] - mu * sc;
        if (which) { g_scale2[t] = sc; g_shift2[t] = sh; }
        else       { g_scale1[t] = sc; g_shift1[t] = sh; }
    }
}

// ---------------- GEMM2 on POOLED rows: HWp = relu(bn1(P/score + b1)) @ Wg ----------------
__global__ __launch_bounds__(128) void k_gemm2(const float* __restrict__ Wg,
                                               const float* __restrict__ score,
                                               const float* __restrict__ b1) {
    __shared__ float Ws[64 * 64];
    __shared__ float Xs[64 * 68];
    int t = threadIdx.x;
    for (int i = t; i < 1024; i += 128)
        ((float4*)Ws)[i] = ((const float4*)Wg)[i];
    int row0 = blockIdx.x * 64;
    for (int i = t; i < 1024; i += 128) {
        int r = i >> 4, c4 = i & 15;
        int row = row0 + r;
        float4 v = make_float4(0.f, 0.f, 0.f, 0.f);
        if (row < NPOOL) {
            float inv = 1.0f / score[row];
            float4 p   = ((const float4*)(g_P + (size_t)row * CH))[c4];
            float4 a   = ((const float4*)g_scale1)[c4];
            float4 sh  = ((const float4*)g_shift1)[c4];
            float4 b1v = ((const float4*)b1)[c4];
            v.x = fmaxf(fmaf(p.x * inv, a.x, fmaf(b1v.x, a.x, sh.x)), 0.f);
            v.y = fmaxf(fmaf(p.y * inv, a.y, fmaf(b1v.y, a.y, sh.y)), 0.f);
            v.z = fmaxf(fmaf(p.z * inv, a.z, fmaf(b1v.z, a.z, sh.z)), 0.f);
            v.w = fmaxf(fmaf(p.w * inv, a.w, fmaf(b1v.w, a.w, sh.w)), 0.f);
        }
        *((float4*)(Xs + r * 68 + c4 * 4)) = v;
    }
    __syncthreads();
    int cg = t & 7, rg = t >> 3;
    float acc[4][8];
#pragma unroll
    for (int r = 0; r < 4; r++)
#pragma unroll
        for (int c = 0; c < 8; c++) acc[r][c] = 0.f;
    for (int k = 0; k < 64; k++) {
        float4 w0 = *((float4*)(Ws + k * 64 + cg * 8));
        float4 w1 = *((float4*)(Ws + k * 64 + cg * 8 + 4));
#pragma unroll
        for (int r = 0; r < 4; r++) {
            float xv = Xs[(rg + 16 * r) * 68 + k];
            acc[r][0] = fmaf(xv, w0.x, acc[r][0]);
            acc[r][1] = fmaf(xv, w0.y, acc[r][1]);
            acc[r][2] = fmaf(xv, w0.z, acc[r][2]);
            acc[r][3] = fmaf(xv, w0.w, acc[r][3]);
            acc[r][4] = fmaf(xv, w1.x, acc[r][4]);
            acc[r][5] = fmaf(xv, w1.y, acc[r][5]);
            acc[r][6] = fmaf(xv, w1.z, acc[r][6]);
            acc[r][7] = fmaf(xv, w1.w, acc[r][7]);
        }
    }
#pragma unroll
    for (int r = 0; r < 4; r++) {
        int row = row0 + rg + 16 * r;
        if (row < NPOOL) {
            size_t base = (size_t)row * CH + cg * 8;
            *((float4*)(g_HWp + base))     = make_float4(acc[r][0], acc[r][1], acc[r][2], acc[r][3]);
            *((float4*)(g_HWp + base + 4)) = make_float4(acc[r][4], acc[r][5], acc[r][6], acc[r][7]);
        }
    }
}

// ---------------- ACC init: ACC[i] = bg + HWp[cluster[i]] * dis[i]^2 (self loop) ----------------
__global__ void k_accinit(const int* __restrict__ cluster, const float* __restrict__ bg) {
    int i4 = blockIdx.x * blockDim.x + threadIdx.x;
    if (i4 < NUN * 16) {
        int row = i4 >> 4, q = i4 & 15;
        int c = cluster[row];
        float dv = g_dis[row];
        float d2 = dv * dv;
        float4 h = ((const float4*)(g_HWp + (size_t)c * CH))[q];
        float4 b = ((const float4*)bg)[q];
        float4 o;
        o.x = fmaf(h.x, d2, b.x);
        o.y = fmaf(h.y, d2, b.y);
        o.z = fmaf(h.z, d2, b.z);
        o.w = fmaf(h.w, d2, b.w);
        ((float4*)g_ACC)[i4] = o;
    }
}

// ---------------- edge scatter: ACC[dst] += HWp[cluster[src]] * dis[src]*dis[dst] ----------------
__global__ void k_scatter(const int* __restrict__ src, const int* __restrict__ dst,
                          const int* __restrict__ cluster) {
    int tid = blockIdx.x * blockDim.x + threadIdx.x;   // NEDGE*16 threads
    if (tid < NEDGE * 16) {
        int e = tid >> 4;
        int q = tid & 15;
        int s = src[e], d = dst[e];
        int c = cluster[s];
        float coef = g_dis[s] * g_dis[d];
        float4 v = *((const float4*)(g_HWp + (size_t)c * CH + q * 4));
        float* p = g_ACC + (size_t)d * CH + q * 4;
        asm volatile("red.global.add.v4.f32 [%0], {%1, %2, %3, %4};"
                     :: "l"(p), "f"(v.x * coef), "f"(v.y * coef),
                        "f"(v.z * coef), "f"(v.w * coef)
                     : "memory");
    }
}

// ---------------- BN2 stats over ACC ----------------
__global__ void k_stats2() {
    int tx = threadIdx.x;
    int ty = threadIdx.y;
    int row0 = blockIdx.x * 64;
    float ls = 0.f, lq = 0.f;
    for (int r = 0; r < 16; r++) {
        int row = row0 + ty + 4 * r;
        if (row < NUN) {
            float v = g_ACC[(size_t)row * CH + tx];
            ls += v;
            lq += v * v;
        }
    }
    __shared__ float ss[4][64], sq[4][64];
    ss[ty][tx] = ls; sq[ty][tx] = lq;
    __syncthreads();
    if (ty == 0) {
        float s = ss[0][tx] + ss[1][tx] + ss[2][tx] + ss[3][tx];
        float q = sq[0][tx] + sq[1][tx] + sq[2][tx] + sq[3][tx];
        atomicAdd(&g_s2[tx], (double)s);
        atomicAdd(&g_q2[tx], (double)q);
    }
}

// ---------------- final: out = relu(bn2(ACC)) ----------------
__global__ void k_final(float* __restrict__ out) {
    int i4 = blockIdx.x * blockDim.x + threadIdx.x;
    if (i4 < NUN * 16) {
        int c4 = i4 & 15;
        float4 v  = ((const float4*)g_ACC)[i4];
        float4 sc = ((const float4*)g_scale2)[c4];
        float4 sh = ((const float4*)g_shift2)[c4];
        float4 o;
        o.x = fmaxf(fmaf(v.x, sc.x, sh.x), 0.f);
        o.y = fmaxf(fmaf(v.y, sc.y, sh.y), 0.f);
        o.z = fmaxf(fmaf(v.z, sc.z, sh.z), 0.f);
        o.w = fmaxf(fmaf(v.w, sc.w, sh.w), 0.f);
        ((float4*)out)[i4] = o;
    }
}

// ---------------- optional tail: edge_index and batch passthrough ----------------
__global__ void k_tail(const int* __restrict__ ei, const int* __restrict__ batch,
                       float* __restrict__ out, int extra) {
    int i = blockIdx.x * blockDim.x + threadIdx.x;
    if (i < extra) {
        float v;
        if (i < 2 * NEDGE) v = (float)ei[i];
        else {
            int j = i - 2 * NEDGE;
            v = (j < NUN) ? (float)batch[j] : 0.f;
        }
        out[NUN * CH + i] = v;
    }
}

// ---------------- launch ----------------
extern "C" void kernel_launch(void* const* d_in, const int* in_sizes, int n_in,
                              void* d_out, int out_size) {
    const float* x       = (const float*)d_in[0];
    const int*   ei      = (const int*)  d_in[1];
    const int*   batch   = (const int*)  d_in[2];
    const int*   cluster = (const int*)  d_in[3];
    const float* score   = (const float*)d_in[4];
    const float* W1      = (const float*)d_in[5];
    const float* b1      = (const float*)d_in[6];
    const float* g1      = (const float*)d_in[7];
    const float* be1     = (const float*)d_in[8];
    const float* Wg      = (const float*)d_in[9];
    const float* bg      = (const float*)d_in[10];
    const float* g2      = (const float*)d_in[11];
    const float* be2     = (const float*)d_in[12];
    const int* srcA = ei;
    const int* dstA = ei + NEDGE;
    float* out = (float*)d_out;

    k_init<<<(NUN + 255) / 256, 256>>>();
    k_deg_hist<<<(NEDGE + 255) / 256, 256>>>(dstA, cluster);
    k_dis<<<(NUN + 255) / 256, 256>>>();
    k_gemm1<<<(NPOOL + 63) / 64, 128>>>(x, W1);
    k_stats1<<<(NPOOL + 63) / 64, dim3(64, 4)>>>(score, b1);
    k_meanvar<<<1, 64>>>(g1, be1, 0);
    k_gemm2<<<(NPOOL + 63) / 64, 128>>>(Wg, score, b1);
    k_accinit<<<(NUN * 16 + 255) / 256, 256>>>(cluster, bg);
    k_scatter<<<(NEDGE * 16 + 255) / 256, 256>>>(srcA, dstA, cluster);
    k_stats2<<<(NUN + 63) / 64, dim3(64, 4)>>>();
    k_meanvar<<<1, 64>>>(g2, be2, 1);
    k_final<<<(NUN * 16 + 255) / 256, 256>>>(out);

    int extra = out_size - NUN * CH;
    if (extra > 0)
        k_tail<<<(extra + 255) / 256, 256>>>(ei, batch, out, extra);
}